// round 3
// baseline (speedup 1.0000x reference)
#include <cuda_runtime.h>
#include <math.h>
#include <stdint.h>
#include <stddef.h>

#define DIM   128
#define NN    20000
#define NNZV  500000
#define EE    5000
#define CC    50
#define NENT  50000
#define NKEY  60000      // 3*NN
#define NHEAD 8
#define DH    16

// ----------------------------- scratch (device globals; no allocs) ----------
__device__ float d_xt  [3 * NN * DIM];        // x @ theta per modality
__device__ float d_me  [3 * EE * DIM];        // hyperedge means
__device__ float d_rel [NKEY * DIM];          // related = [ih; eh; wh]
__device__ float d_Kb  [NKEY * DIM];
__device__ float d_Vb  [NKEY * DIM];
__device__ float d_qb  [CC * DIM];
__device__ float d_S   [NHEAD * CC * NKEY];   // attention scores (96MB)
__device__ float d_mstat[NHEAD * CC];
__device__ float d_lstat[NHEAD * CC];         // stores 1/l
__device__ float d_headout[CC * DIM];         // pre-Wo attention output (accumulated)
__device__ float d_att [CC * DIM];            // attentive = headout@Wo+bo
__device__ float d_u   [DIM];
__device__ float d_urepr[DIM];

__device__ int d_ecnt[3 * EE];
__device__ int d_eoff[3 * (EE + 1)];
__device__ int d_ecur[3 * EE];
__device__ int d_ncnt[3 * NN];
__device__ int d_noff[3 * (NN + 1)];
__device__ int d_ncur[3 * NN];
__device__ int d_csrE[3 * NNZV];              // per-edge entry lists (node ids)
__device__ int d_csrN[3 * NNZV];              // per-node entry lists (edge ids)

// tag -> device-global pointer (avoids cudaGetSymbolAddress on the host)
#define TAG_XT0 0
#define TAG_XT1 1
#define TAG_XT2 2
#define TAG_REL 3
#define TAG_K   4
#define TAG_V   5
#define TAG_Q   6
#define TAG_HO  7
#define TAG_ATT 8
__device__ __forceinline__ float* tag_ptr(int t) {
    switch (t) {
        case TAG_XT0: return d_xt;
        case TAG_XT1: return d_xt + (size_t)NN * DIM;
        case TAG_XT2: return d_xt + (size_t)2 * NN * DIM;
        case TAG_REL: return d_rel;
        case TAG_K:   return d_Kb;
        case TAG_V:   return d_Vb;
        case TAG_Q:   return d_qb;
        case TAG_HO:  return d_headout;
        case TAG_ATT: return d_att;
    }
    return nullptr;
}

// ----------------------------- zero accumulators ----------------------------
__global__ void zero_kernel() {
    int i = blockIdx.x * blockDim.x + threadIdx.x;
    if (i < 3 * EE)   d_ecnt[i] = 0;
    if (i < 3 * NN)   d_ncnt[i] = 0;
    if (i < CC * DIM) d_headout[i] = 0.f;
}

// ----------------------------- CSR build ------------------------------------
__global__ void count_kernel(const int* __restrict__ nodes,
                             const int* __restrict__ edges, int mod) {
    int i = blockIdx.x * blockDim.x + threadIdx.x;
    if (i >= NNZV) return;
    atomicAdd(&d_ecnt[mod * EE + edges[i]], 1);
    atomicAdd(&d_ncnt[mod * NN + nodes[i]], 1);
}

__global__ void scan_kernel() {
    // blocks 0..2: edge counts per modality; blocks 3..5: node counts
    __shared__ int s[1024];
    __shared__ int srun;
    int b = blockIdx.x;
    int mod = b % 3;
    bool isE = (b < 3);
    int len = isE ? EE : NN;
    const int* cnt = isE ? (d_ecnt + mod * EE) : (d_ncnt + mod * NN);
    int* off = isE ? (d_eoff + mod * (EE + 1)) : (d_noff + mod * (NN + 1));
    int* cur = isE ? (d_ecur + mod * EE) : (d_ncur + mod * NN);
    int tid = threadIdx.x;
    if (tid == 0) srun = 0;
    __syncthreads();
    for (int base = 0; base < len; base += 1024) {
        int v = (base + tid < len) ? cnt[base + tid] : 0;
        s[tid] = v;
        __syncthreads();
        for (int d = 1; d < 1024; d <<= 1) {
            int t = (tid >= d) ? s[tid - d] : 0;
            __syncthreads();
            s[tid] += t;
            __syncthreads();
        }
        int run = srun;
        if (base + tid < len) {
            int ex = run + s[tid] - v;
            off[base + tid] = ex;
            cur[base + tid] = ex;
        }
        __syncthreads();
        if (tid == 1023) srun = run + s[1023];
        __syncthreads();
    }
    if (tid == 0) off[len] = srun;
}

__global__ void scatter_kernel(const int* __restrict__ nodes,
                               const int* __restrict__ edges, int mod) {
    int i = blockIdx.x * blockDim.x + threadIdx.x;
    if (i >= NNZV) return;
    int e = edges[i], n = nodes[i];
    int pe = atomicAdd(&d_ecur[mod * EE + e], 1);
    d_csrE[mod * NNZV + pe] = n;
    int pn = atomicAdd(&d_ncur[mod * NN + n], 1);
    d_csrN[mod * NNZV + pn] = e;
}

// ----------------------------- generic 128x128 GEMM -------------------------
// C[M,128] = A[M,128] @ W[128,128] (+ bias) ; block: 256 thr, 64 rows
// A source: Aext if non-null, else tag_ptr(Atag). C dest: tag_ptr(Ctag).
__global__ void gemm128(const float* __restrict__ Aext, int Atag,
                        const float* __restrict__ W,
                        const float* __restrict__ bias, int Ctag, int M) {
    const float* A = (Aext != nullptr) ? Aext : tag_ptr(Atag);
    float* C = tag_ptr(Ctag);
    __shared__ float As[64 * 32];
    __shared__ float Ws[32 * 128];
    int tid = threadIdx.x;
    int warp = tid >> 5, lane = tid & 31;
    int row0 = blockIdx.x * 64;
    float acc[8][4];
#pragma unroll
    for (int r = 0; r < 8; r++) { acc[r][0] = acc[r][1] = acc[r][2] = acc[r][3] = 0.f; }

    for (int k0 = 0; k0 < 128; k0 += 32) {
#pragma unroll
        for (int i = 0; i < 2; i++) {            // load A tile 64x32
            int idx = tid + i * 256;             // float4 index
            int r = idx >> 3, c = (idx & 7) * 4;
            float4 v = make_float4(0.f, 0.f, 0.f, 0.f);
            if (row0 + r < M) v = *(const float4*)&A[(size_t)(row0 + r) * 128 + k0 + c];
            *(float4*)&As[r * 32 + c] = v;
        }
#pragma unroll
        for (int i = 0; i < 4; i++) {            // load W tile 32x128
            int idx = tid + i * 256;
            int r = idx >> 5, c = (idx & 31) * 4;
            *(float4*)&Ws[r * 128 + c] = *(const float4*)&W[(size_t)(k0 + r) * 128 + c];
        }
        __syncthreads();
#pragma unroll
        for (int kk = 0; kk < 32; kk++) {
            float4 w = *(float4*)&Ws[kk * 128 + lane * 4];
#pragma unroll
            for (int r = 0; r < 8; r++) {
                float a = As[(warp * 8 + r) * 32 + kk];
                acc[r][0] += a * w.x; acc[r][1] += a * w.y;
                acc[r][2] += a * w.z; acc[r][3] += a * w.w;
            }
        }
        __syncthreads();
    }
    float4 bv = make_float4(0.f, 0.f, 0.f, 0.f);
    if (bias != nullptr) bv = *(const float4*)&bias[lane * 4];
#pragma unroll
    for (int r = 0; r < 8; r++) {
        int row = row0 + warp * 8 + r;
        if (row < M) {
            float4 o = make_float4(acc[r][0] + bv.x, acc[r][1] + bv.y,
                                   acc[r][2] + bv.z, acc[r][3] + bv.w);
            *(float4*)&C[(size_t)row * 128 + lane * 4] = o;
        }
    }
}

// ----------------------------- hyperedge means (warp per edge) ---------------
__global__ void edge_mean_kernel() {
    int gw = (blockIdx.x * blockDim.x + threadIdx.x) >> 5;
    int lane = threadIdx.x & 31;
    if (gw >= 3 * EE) return;
    int mod = gw / EE, e = gw - mod * EE;
    const int* base = d_csrE + mod * NNZV;
    int s0 = d_eoff[mod * (EE + 1) + e];
    int s1 = d_eoff[mod * (EE + 1) + e + 1];
    const float* xtm = d_xt + (size_t)mod * NN * DIM;
    float4 acc = make_float4(0.f, 0.f, 0.f, 0.f);
    int j = s0;
    for (; j + 4 <= s1; j += 4) {
        int n0 = base[j], n1 = base[j + 1], n2 = base[j + 2], n3 = base[j + 3];
        float4 v0 = *(const float4*)&xtm[(size_t)n0 * DIM + lane * 4];
        float4 v1 = *(const float4*)&xtm[(size_t)n1 * DIM + lane * 4];
        float4 v2 = *(const float4*)&xtm[(size_t)n2 * DIM + lane * 4];
        float4 v3 = *(const float4*)&xtm[(size_t)n3 * DIM + lane * 4];
        acc.x += (v0.x + v1.x) + (v2.x + v3.x);
        acc.y += (v0.y + v1.y) + (v2.y + v3.y);
        acc.z += (v0.z + v1.z) + (v2.z + v3.z);
        acc.w += (v0.w + v1.w) + (v2.w + v3.w);
    }
    for (; j < s1; j++) {
        int n0 = base[j];
        float4 v0 = *(const float4*)&xtm[(size_t)n0 * DIM + lane * 4];
        acc.x += v0.x; acc.y += v0.y; acc.z += v0.z; acc.w += v0.w;
    }
    int deg = s1 - s0; if (deg < 1) deg = 1;
    float inv = 1.f / (float)deg;
    *(float4*)&d_me[((size_t)mod * EE + e) * DIM + lane * 4] =
        make_float4(acc.x * inv, acc.y * inv, acc.z * inv, acc.w * inv);
}

// ----------------------------- node output (warp per node) -------------------
__global__ void node_out_kernel(const float* __restrict__ bias_item,
                                const float* __restrict__ bias_entity,
                                const float* __restrict__ bias_word) {
    int gw = (blockIdx.x * blockDim.x + threadIdx.x) >> 5;
    int lane = threadIdx.x & 31;
    if (gw >= 3 * NN) return;
    int mod = gw / NN, n = gw - mod * NN;
    const int* base = d_csrN + mod * NNZV;
    int s0 = d_noff[mod * (NN + 1) + n];
    int s1 = d_noff[mod * (NN + 1) + n + 1];
    const float* mem = d_me + (size_t)mod * EE * DIM;
    float4 acc = make_float4(0.f, 0.f, 0.f, 0.f);
    int j = s0;
    for (; j + 4 <= s1; j += 4) {
        int e0 = base[j], e1 = base[j + 1], e2 = base[j + 2], e3 = base[j + 3];
        float4 v0 = *(const float4*)&mem[(size_t)e0 * DIM + lane * 4];
        float4 v1 = *(const float4*)&mem[(size_t)e1 * DIM + lane * 4];
        float4 v2 = *(const float4*)&mem[(size_t)e2 * DIM + lane * 4];
        float4 v3 = *(const float4*)&mem[(size_t)e3 * DIM + lane * 4];
        acc.x += (v0.x + v1.x) + (v2.x + v3.x);
        acc.y += (v0.y + v1.y) + (v2.y + v3.y);
        acc.z += (v0.z + v1.z) + (v2.z + v3.z);
        acc.w += (v0.w + v1.w) + (v2.w + v3.w);
    }
    for (; j < s1; j++) {
        int e0 = base[j];
        float4 v0 = *(const float4*)&mem[(size_t)e0 * DIM + lane * 4];
        acc.x += v0.x; acc.y += v0.y; acc.z += v0.z; acc.w += v0.w;
    }
    int deg = s1 - s0; if (deg < 1) deg = 1;
    float inv = 1.f / (float)deg;
    const float* bias = (mod == 0) ? bias_item : (mod == 1) ? bias_entity : bias_word;
    float4 bv = *(const float4*)&bias[lane * 4];
    *(float4*)&d_rel[((size_t)mod * NN + n) * DIM + lane * 4] =
        make_float4(acc.x * inv + bv.x, acc.y * inv + bv.y,
                    acc.z * inv + bv.z, acc.w * inv + bv.w);
}

// ----------------------------- attention scores ------------------------------
// grid: NHEAD * SCORE_TILES; thread = one key, K head-slice in registers.
#define SCORE_TILES 235
__global__ void scores_kernel() {
    int bx = blockIdx.x;
    int h = bx / SCORE_TILES;
    int k0 = (bx % SCORE_TILES) * 256;
    int key = k0 + threadIdx.x;
    __shared__ float qs[CC * DH];
    for (int i = threadIdx.x; i < CC * DH; i += 256) {
        int q = i / DH, d = i % DH;
        qs[i] = d_qb[q * DIM + h * DH + d];
    }
    float4 kv0, kv1, kv2, kv3;
    bool valid = key < NKEY;
    if (valid) {
        const float* kr = d_Kb + (size_t)key * DIM + h * DH;
        kv0 = *(const float4*)(kr + 0);
        kv1 = *(const float4*)(kr + 4);
        kv2 = *(const float4*)(kr + 8);
        kv3 = *(const float4*)(kr + 12);
    }
    __syncthreads();
    if (!valid) return;
    float* Sh = d_S + (size_t)h * CC * NKEY + key;
#pragma unroll 5
    for (int q = 0; q < CC; q++) {
        const float4* qp = (const float4*)&qs[q * DH];
        float4 q0 = qp[0], q1 = qp[1], q2 = qp[2], q3 = qp[3];
        float acc = q0.x * kv0.x + q0.y * kv0.y + q0.z * kv0.z + q0.w * kv0.w
                  + q1.x * kv1.x + q1.y * kv1.y + q1.z * kv1.z + q1.w * kv1.w
                  + q2.x * kv2.x + q2.y * kv2.y + q2.z * kv2.z + q2.w * kv2.w
                  + q3.x * kv3.x + q3.y * kv3.y + q3.z * kv3.z + q3.w * kv3.w;
        Sh[(size_t)q * NKEY] = acc * 0.25f;   // / sqrt(16)
    }
}

// ----------------------------- softmax stats (block per (h,q)) ---------------
__global__ void stats_kernel() {
    int hq = blockIdx.x;
    const float* row = d_S + (size_t)hq * NKEY;
    float m = -1e30f, l = 0.f;
    for (int k = threadIdx.x; k < NKEY; k += 256) {
        float s = row[k];
        if (s > m) { l = l * __expf(m - s) + 1.f; m = s; }
        else       { l += __expf(s - m); }
    }
    __shared__ float sm[256], sl[256];
    sm[threadIdx.x] = m; sl[threadIdx.x] = l;
    __syncthreads();
    for (int o = 128; o; o >>= 1) {
        if (threadIdx.x < o) {
            float m2 = sm[threadIdx.x + o], l2 = sl[threadIdx.x + o];
            float M = fmaxf(sm[threadIdx.x], m2);
            sl[threadIdx.x] = sl[threadIdx.x] * __expf(sm[threadIdx.x] - M)
                            + l2 * __expf(m2 - M);
            sm[threadIdx.x] = M;
        }
        __syncthreads();
    }
    if (threadIdx.x == 0) { d_mstat[hq] = sm[0]; d_lstat[hq] = 1.f / sl[0]; }
}

// ----------------------------- weighted V accumulation -----------------------
#define WV_CH 128
#define WV_CHUNKS 469
__global__ void wv_kernel() {
    int bx = blockIdx.x;
    int h = bx / WV_CHUNKS;
    int k0 = (bx % WV_CHUNKS) * WV_CH;
    int kmax = NKEY - k0; if (kmax > WV_CH) kmax = WV_CH;
    __shared__ float wsm[CC * 132];          // padded stride -> conflict-free
    __shared__ float4 vsm[WV_CH * 4];        // vsm[k*4+dg] = V[k0+k][h*16+dg*4..]
    int tid = threadIdx.x;
    for (int i = tid; i < WV_CH * 4; i += 256) {
        int k = i >> 2, dg = i & 3;
        float4 v = make_float4(0.f, 0.f, 0.f, 0.f);
        if (k < kmax) v = *(const float4*)&d_Vb[(size_t)(k0 + k) * DIM + h * DH + dg * 4];
        vsm[i] = v;
    }
    for (int i = tid; i < CC * WV_CH; i += 256) {
        int q = i / WV_CH, k = i - q * WV_CH;
        float w = 0.f;
        if (k < kmax) {
            int hq = h * CC + q;
            w = __expf(d_S[(size_t)hq * NKEY + k0 + k] - d_mstat[hq]) * d_lstat[hq];
        }
        wsm[q * 132 + k] = w;
    }
    __syncthreads();
    if (tid < CC * 4) {
        int q = tid >> 2, dg = tid & 3;
        float4 acc = make_float4(0.f, 0.f, 0.f, 0.f);
        const float* wr = wsm + q * 132;
#pragma unroll 4
        for (int k = 0; k < WV_CH; k++) {
            float w = wr[k];
            float4 v = vsm[k * 4 + dg];
            acc.x += w * v.x; acc.y += w * v.y; acc.z += w * v.z; acc.w += w * v.w;
        }
        float* dst = d_headout + q * DIM + h * DH + dg * 4;
        atomicAdd(dst + 0, acc.x); atomicAdd(dst + 1, acc.y);
        atomicAdd(dst + 2, acc.z); atomicAdd(dst + 3, acc.w);
    }
}

// ----------------------------- self attention (single block, 128 thr) --------
// which==0: H = d_att (R=CC),        out = d_u
// which==1: H = Hext (ctx, R=CC+1 with last row = d_u), out = d_urepr
__global__ void selfattn_kernel(const float* __restrict__ Hext, int R, int which,
                                const float* __restrict__ A,
                                const float* __restrict__ Bv) {
    int d = threadIdx.x;                     // 128 threads
    const float* Hm = (which == 0) ? d_att : Hext;
    float* out = (which == 0) ? d_u : d_urepr;
    __shared__ float es[64];
    __shared__ float red[4];
    __shared__ float ws[64];
    for (int r = 0; r < R; r++) {
        const float* hr = (which == 1 && r == R - 1) ? d_u : (Hm + (size_t)r * DIM);
        float a0 = 0.f, a1 = 0.f, a2 = 0.f, a3 = 0.f;
#pragma unroll 8
        for (int k = 0; k < DIM; k += 4) {
            a0 += hr[k + 0] * A[(size_t)(k + 0) * DIM + d];
            a1 += hr[k + 1] * A[(size_t)(k + 1) * DIM + d];
            a2 += hr[k + 2] * A[(size_t)(k + 2) * DIM + d];
            a3 += hr[k + 3] * A[(size_t)(k + 3) * DIM + d];
        }
        float v = tanhf((a0 + a1) + (a2 + a3)) * Bv[d];
        for (int o = 16; o; o >>= 1) v += __shfl_down_sync(0xffffffffu, v, o);
        if ((d & 31) == 0) red[d >> 5] = v;
        __syncthreads();
        if (d == 0) es[r] = (red[0] + red[1]) + (red[2] + red[3]);
        __syncthreads();
    }
    if (d == 0) {
        float m = -1e30f;
        for (int r = 0; r < R; r++) m = fmaxf(m, es[r]);
        float s = 0.f;
        for (int r = 0; r < R; r++) { float w = __expf(es[r] - m); ws[r] = w; s += w; }
        float inv = 1.f / s;
        for (int r = 0; r < R; r++) ws[r] *= inv;
    }
    __syncthreads();
    float o = 0.f;
    for (int r = 0; r < R; r++) {
        const float* hr = (which == 1 && r == R - 1) ? d_u : (Hm + (size_t)r * DIM);
        o += ws[r] * hr[d];
    }
    out[d] = o;
}

// ----------------------------- final recommendation GEMV ---------------------
__global__ void recscore_kernel(const float* __restrict__ W,
                                const float* __restrict__ b,
                                float* __restrict__ out) {
    __shared__ float us[DIM];
    int tid = threadIdx.x;
    if (tid < DIM) us[tid] = d_urepr[tid];
    __syncthreads();
    int j = blockIdx.x * 256 + tid;
    if (j >= NENT) return;
    float a0 = 0.f, a1 = 0.f, a2 = 0.f, a3 = 0.f;
#pragma unroll
    for (int d = 0; d < DIM; d += 4) {
        a0 += us[d + 0] * W[(size_t)(d + 0) * NENT + j];
        a1 += us[d + 1] * W[(size_t)(d + 1) * NENT + j];
        a2 += us[d + 2] * W[(size_t)(d + 2) * NENT + j];
        a3 += us[d + 3] * W[(size_t)(d + 3) * NENT + j];
    }
    out[j] = (a0 + a1) + (a2 + a3) + b[j];
}

// ----------------------------- launch ----------------------------------------
extern "C" void kernel_launch(void* const* d_in, const int* in_sizes, int n_in,
                              void* d_out, int out_size) {
    const float* item_emb     = (const float*)d_in[0];
    const float* entity_emb   = (const float*)d_in[1];
    const float* word_emb     = (const float*)d_in[2];
    const float* context_ent  = (const float*)d_in[3];
    const float* theta_item   = (const float*)d_in[4];
    const float* bias_item    = (const float*)d_in[5];
    const float* theta_entity = (const float*)d_in[6];
    const float* bias_entity  = (const float*)d_in[7];
    const float* theta_word   = (const float*)d_in[8];
    const float* bias_word    = (const float*)d_in[9];
    const float* Wq = (const float*)d_in[10];  const float* bq = (const float*)d_in[11];
    const float* Wk = (const float*)d_in[12];  const float* bk = (const float*)d_in[13];
    const float* Wv = (const float*)d_in[14];  const float* bv = (const float*)d_in[15];
    const float* Wo = (const float*)d_in[16];  const float* bo = (const float*)d_in[17];
    const float* a_his = (const float*)d_in[18]; const float* b_his = (const float*)d_in[19];
    const float* a_kg  = (const float*)d_in[20]; const float* b_kg  = (const float*)d_in[21];
    const float* rec_W = (const float*)d_in[22]; const float* rec_b = (const float*)d_in[23];
    const int* item_nodes   = (const int*)d_in[24];
    const int* item_edges   = (const int*)d_in[25];
    const int* entity_nodes = (const int*)d_in[26];
    const int* entity_edges = (const int*)d_in[27];
    const int* word_nodes   = (const int*)d_in[28];
    const int* word_edges   = (const int*)d_in[29];
    float* out = (float*)d_out;

    // 1) zero accumulators / counters
    zero_kernel<<<(3 * NN + 255) / 256, 256>>>();

    // 2) xt = x @ theta  (NO bias here — bias is applied after aggregation)
    gemm128<<<(NN + 63) / 64, 256>>>(item_emb,   -1, theta_item,   nullptr, TAG_XT0, NN);
    gemm128<<<(NN + 63) / 64, 256>>>(entity_emb, -1, theta_entity, nullptr, TAG_XT1, NN);
    gemm128<<<(NN + 63) / 64, 256>>>(word_emb,   -1, theta_word,   nullptr, TAG_XT2, NN);

    // 3) CSR build
    count_kernel<<<(NNZV + 255) / 256, 256>>>(item_nodes,   item_edges,   0);
    count_kernel<<<(NNZV + 255) / 256, 256>>>(entity_nodes, entity_edges, 1);
    count_kernel<<<(NNZV + 255) / 256, 256>>>(word_nodes,   word_edges,   2);
    scan_kernel<<<6, 1024>>>();
    scatter_kernel<<<(NNZV + 255) / 256, 256>>>(item_nodes,   item_edges,   0);
    scatter_kernel<<<(NNZV + 255) / 256, 256>>>(entity_nodes, entity_edges, 1);
    scatter_kernel<<<(NNZV + 255) / 256, 256>>>(word_nodes,   word_edges,   2);

    // 4) hyperedge means, then node outputs (+bias) -> related
    edge_mean_kernel<<<(3 * EE + 7) / 8, 256>>>();
    node_out_kernel<<<(3 * NN + 7) / 8, 256>>>(bias_item, bias_entity, bias_word);

    // 5) K/V/q projections
    gemm128<<<(NKEY + 63) / 64, 256>>>(nullptr, TAG_REL, Wk, bk, TAG_K, NKEY);
    gemm128<<<(NKEY + 63) / 64, 256>>>(nullptr, TAG_REL, Wv, bv, TAG_V, NKEY);
    gemm128<<<1, 256>>>(context_ent, -1, Wq, bq, TAG_Q, CC);

    // 6) attention
    scores_kernel<<<NHEAD * SCORE_TILES, 256>>>();
    stats_kernel<<<NHEAD * CC, 256>>>();
    wv_kernel<<<NHEAD * WV_CHUNKS, 256>>>();
    gemm128<<<1, 256>>>(nullptr, TAG_HO, Wo, bo, TAG_ATT, CC);

    // 7) self attentions
    selfattn_kernel<<<1, 128>>>(nullptr,     CC,     0, a_his, b_his);
    selfattn_kernel<<<1, 128>>>(context_ent, CC + 1, 1, a_kg,  b_kg);

    // 8) final scores
    recscore_kernel<<<(NENT + 255) / 256, 256>>>(rec_W, rec_b, out);
}